// round 2
// baseline (speedup 1.0000x reference)
#include <cuda_runtime.h>
#include <math.h>

// ---------------- scratch (device globals; no allocations allowed) ----------
__device__ float g_q[8192 * 4096];
__device__ float g_k[8192 * 4096];
__device__ float g_v[8192 * 4096];
__device__ float g_ep[67108864]; // 8192*8192

// ---------------- helpers ----------------------------------------------------
__device__ __forceinline__ unsigned f2tf(float x) {
    unsigned u;
    asm("cvt.rna.tf32.f32 %0, %1;" : "=r"(u) : "f"(x));
    return u;
}

__device__ __forceinline__ unsigned lds_tf(const float* p) {
    return f2tf(*p);
}

__device__ __forceinline__ void cpasync16(unsigned saddr, const float* gaddr) {
    asm volatile("cp.async.cg.shared.global [%0], [%1], 16;\n" ::"r"(saddr), "l"(gaddr));
}
__device__ __forceinline__ void cp_commit() {
    asm volatile("cp.async.commit_group;\n" ::);
}
template <int N>
__device__ __forceinline__ void cp_wait() {
    asm volatile("cp.async.wait_group %0;\n" ::"n"(N));
}

#define MMA8(C, A, Bv)                                                         \
    asm volatile(                                                              \
        "mma.sync.aligned.m16n8k8.row.col.f32.tf32.tf32.f32 "                  \
        "{%0,%1,%2,%3}, {%4,%5,%6,%7}, {%8,%9}, {%0,%1,%2,%3};"                \
        : "+f"(C[0]), "+f"(C[1]), "+f"(C[2]), "+f"(C[3])                       \
        : "r"(A[0]), "r"(A[1]), "r"(A[2]), "r"(A[3]), "r"(Bv[0]), "r"(Bv[1]))

// ---------------- GEMM: C[M,N] = A[M,K] * B[N,K]^T (+bias[n]) ---------------
// tf32 tensor-core GEMM, 128x128 block tile, cp.async 5-stage pipeline (K=16
// per stage), 8 warps (2m x 4n), 64x32 warp tile, 2 CTAs/SM.
#define GBM 128
#define GBN 128
#define GKS 16                      // K per stage
#define NSTAGE 5
#define RPAD 20                     // row stride in floats (16B-aligned, bank-clean)
#define ASTG (GBM * RPAD)           // 2560 floats per stage per matrix
#define GEMM_SMEM (2 * NSTAGE * ASTG * 4) // 102400 B

__global__ void __launch_bounds__(256, 2)
    gemm_tf32(const float* __restrict__ A, const float* __restrict__ B,
              const float* __restrict__ bias, float* __restrict__ C,
              int M, int N, int K) {
    extern __shared__ float sm[];
    float* As = sm;                    // [NSTAGE][128][20]
    float* Bs = sm + NSTAGE * ASTG;    // [NSTAGE][128][20]

    const unsigned smA_u = (unsigned)__cvta_generic_to_shared(As);
    const unsigned smB_u = (unsigned)__cvta_generic_to_shared(Bs);

    const int tid = threadIdx.x;
    const int lane = tid & 31;
    const int wid = tid >> 5;
    const int g = lane >> 2;   // 0..7
    const int t4 = lane & 3;   // 0..3
    const int wm = (wid & 1) * 64;
    const int wn = (wid >> 1) * 32;

    const int bm = blockIdx.y * GBM;
    const int bn = blockIdx.x * GBN;

    // cp.async thread mapping: 512 16B-vectors per matrix per stage,
    // 2 per thread. vec v -> row v>>2, col (v&3)*4.
    const int r0 = tid >> 2;           // 0..63
    const int r1 = r0 + 64;            // 64..127
    const int c0 = (tid & 3) * 4;      // 0,4,8,12

    const float* Ag0 = A + (size_t)(bm + r0) * K + c0;
    const float* Ag1 = A + (size_t)(bm + r1) * K + c0;
    const float* Bg0 = B + (size_t)(bn + r0) * K + c0;
    const float* Bg1 = B + (size_t)(bn + r1) * K + c0;

    const unsigned sA0 = smA_u + (unsigned)(r0 * RPAD + c0) * 4u;
    const unsigned sA1 = smA_u + (unsigned)(r1 * RPAD + c0) * 4u;
    const unsigned sB0 = smB_u + (unsigned)(r0 * RPAD + c0) * 4u;
    const unsigned sB1 = smB_u + (unsigned)(r1 * RPAD + c0) * 4u;

    const int NT = K / GKS;            // 256 k-tiles
    const unsigned stg_b = ASTG * 4u;  // stage stride in bytes

    // prologue: preload NSTAGE-1 tiles
#pragma unroll
    for (int s = 0; s < NSTAGE - 1; s++) {
        const size_t ko = (size_t)s * GKS;
        cpasync16(sA0 + s * stg_b, Ag0 + ko);
        cpasync16(sA1 + s * stg_b, Ag1 + ko);
        cpasync16(sB0 + s * stg_b, Bg0 + ko);
        cpasync16(sB1 + s * stg_b, Bg1 + ko);
        cp_commit();
    }

    float c[4][4][4];
#pragma unroll
    for (int i = 0; i < 4; i++)
#pragma unroll
        for (int j = 0; j < 4; j++)
#pragma unroll
            for (int q = 0; q < 4; q++) c[i][j][q] = 0.f;

    int stage = 0;
    for (int kt = 0; kt < NT; kt++) {
        cp_wait<NSTAGE - 2>();
        __syncthreads();

        // issue loads for tile kt + NSTAGE-1 into the stage we just freed
        {
            const int kf = kt + NSTAGE - 1;
            if (kf < NT) {
                const int sw = (stage + NSTAGE - 1 >= NSTAGE) ? stage - 1
                                                              : stage + NSTAGE - 1;
                const size_t ko = (size_t)kf * GKS;
                const unsigned so = sw * stg_b;
                cpasync16(sA0 + so, Ag0 + ko);
                cpasync16(sA1 + so, Ag1 + ko);
                cpasync16(sB0 + so, Bg0 + ko);
                cpasync16(sB1 + so, Bg1 + ko);
            }
            cp_commit();
        }

        const float* as = As + stage * ASTG;
        const float* bs = Bs + stage * ASTG;
#pragma unroll
        for (int ks = 0; ks < 2; ks++) {
            const int k0 = ks * 8;
            unsigned af[4][4], bf[4][2];
#pragma unroll
            for (int mf = 0; mf < 4; mf++) {
                const float* p = as + (wm + mf * 16 + g) * RPAD + k0 + t4;
                af[mf][0] = lds_tf(p);
                af[mf][1] = lds_tf(p + 8 * RPAD);
                af[mf][2] = lds_tf(p + 4);
                af[mf][3] = lds_tf(p + 8 * RPAD + 4);
            }
#pragma unroll
            for (int nf = 0; nf < 4; nf++) {
                const float* p = bs + (wn + nf * 8 + g) * RPAD + k0 + t4;
                bf[nf][0] = lds_tf(p);
                bf[nf][1] = lds_tf(p + 4);
            }
#pragma unroll
            for (int mf = 0; mf < 4; mf++)
#pragma unroll
                for (int nf = 0; nf < 4; nf++) MMA8(c[mf][nf], af[mf], bf[nf]);
        }
        stage = (stage + 1 == NSTAGE) ? 0 : stage + 1;
    }

    // epilogue
#pragma unroll
    for (int mf = 0; mf < 4; mf++) {
        const int r = bm + wm + mf * 16 + g;
#pragma unroll
        for (int nf = 0; nf < 4; nf++) {
            const int col = bn + wn + nf * 8 + 2 * t4;
            float b0 = 0.f, b1 = 0.f;
            if (bias) { b0 = bias[col]; b1 = bias[col + 1]; }
            *(float2*)(C + (size_t)r * N + col) =
                make_float2(c[mf][nf][0] + b0, c[mf][nf][1] + b1);
            *(float2*)(C + (size_t)(r + 8) * N + col) =
                make_float2(c[mf][nf][2] + b0, c[mf][nf][3] + b1);
        }
    }
}

// ---------------- fused attention (unchanged from R1) ------------------------
#define AQ 64
#define AS 64
#define QSTR 260
#define KSTR 260
#define VSTR 264
#define SSTR 68
#define ATTN_SMEM ((AQ * QSTR + AS * KSTR + AS * VSTR + AQ * SSTR + 3 * AQ) * 4)

__global__ void __launch_bounds__(256, 1)
    attn_tf32(const float* __restrict__ Q, const float* __restrict__ Kk,
              const float* __restrict__ V, const float* __restrict__ EP,
              float* __restrict__ O) {
    extern __shared__ float sm[];
    float* Qs = sm;
    float* Ks = Qs + AQ * QSTR;
    float* Vs = Ks + AS * KSTR;
    float* Ss = Vs + AS * VSTR;
    float* rM = Ss + AQ * SSTR;
    float* rL = rM + AQ;
    float* rC = rL + AQ;

    const int tid = threadIdx.x;
    const int lane = tid & 31;
    const int wid = tid >> 5;
    const int g = lane >> 2, t4 = lane & 3;
    const int wm = (wid & 3) * 16;
    const int wn = (wid >> 2) * 128;
    const int wns = (wid >> 2) * 32;

    const int b = blockIdx.y >> 4;
    const int h = blockIdx.y & 15;
    const int q0 = blockIdx.x * AQ;

    const float* qg = Q + ((size_t)(b * 512 + q0)) * 4096 + h * 256;
    const float* kg = Kk + ((size_t)(b * 512)) * 4096 + h * 256;
    const float* vg = V + ((size_t)(b * 512)) * 4096 + h * 256;
    const float* eg = EP + ((size_t)(b * 512 + q0)) * 8192 + h * 512;
    float* og = O + ((size_t)(b * 512 + q0)) * 4096 + h * 256;

    const float qscale = 0.0625f; // 1/sqrt(256)
    for (int i = tid; i < AQ * 64; i += 256) {
        int r = i >> 6, ccol = (i & 63) << 2;
        float4 qv = *(const float4*)(qg + (size_t)r * 4096 + ccol);
        *(uint4*)(Qs + r * QSTR + ccol) =
            make_uint4(f2tf(qv.x * qscale), f2tf(qv.y * qscale),
                       f2tf(qv.z * qscale), f2tf(qv.w * qscale));
    }
    if (tid < AQ) { rM[tid] = -1e30f; rL[tid] = 0.f; }

    float o[16][4];
#pragma unroll
    for (int nf = 0; nf < 16; nf++)
#pragma unroll
        for (int q = 0; q < 4; q++) o[nf][q] = 0.f;

    for (int kc = 0; kc < 8; kc++) {
        __syncthreads();
        for (int i = tid; i < AS * 64; i += 256) {
            int r = i >> 6, ccol = (i & 63) << 2;
            float4 kv = *(const float4*)(kg + (size_t)(kc * AS + r) * 4096 + ccol);
            float4 vv = *(const float4*)(vg + (size_t)(kc * AS + r) * 4096 + ccol);
            *(uint4*)(Ks + r * KSTR + ccol) =
                make_uint4(f2tf(kv.x), f2tf(kv.y), f2tf(kv.z), f2tf(kv.w));
            *(uint4*)(Vs + r * VSTR + ccol) =
                make_uint4(f2tf(vv.x), f2tf(vv.y), f2tf(vv.z), f2tf(vv.w));
        }
        __syncthreads();

        float sacc[4][4];
#pragma unroll
        for (int nf = 0; nf < 4; nf++)
#pragma unroll
            for (int q = 0; q < 4; q++) sacc[nf][q] = 0.f;
#pragma unroll
        for (int ks = 0; ks < 32; ks++) {
            const int k0 = ks * 8;
            unsigned af[4];
            const float* pa = Qs + (wm + g) * QSTR + k0 + t4;
            af[0] = __float_as_uint(pa[0]);
            af[1] = __float_as_uint(pa[8 * QSTR]);
            af[2] = __float_as_uint(pa[4]);
            af[3] = __float_as_uint(pa[8 * QSTR + 4]);
#pragma unroll
            for (int nf = 0; nf < 4; nf++) {
                unsigned bf[2];
                const float* pb = Ks + (wns + nf * 8 + g) * KSTR + k0 + t4;
                bf[0] = __float_as_uint(pb[0]);
                bf[1] = __float_as_uint(pb[4]);
                MMA8(sacc[nf], af, bf);
            }
        }
#pragma unroll
        for (int nf = 0; nf < 4; nf++) {
            const int cc = wns + nf * 8 + 2 * t4;
            *(float2*)(Ss + (wm + g) * SSTR + cc) = make_float2(sacc[nf][0], sacc[nf][1]);
            *(float2*)(Ss + (wm + 8 + g) * SSTR + cc) = make_float2(sacc[nf][2], sacc[nf][3]);
        }
        __syncthreads();

        {
            const int r = tid >> 2, sub = tid & 3;
            float sv[16];
            const float* ep4 = eg + (size_t)r * 8192 + kc * 64 + sub * 16;
            float* srow = Ss + r * SSTR + sub * 16;
#pragma unroll
            for (int j = 0; j < 4; j++) {
                float4 e = *(const float4*)(ep4 + j * 4);
                float4 s = *(const float4*)(srow + j * 4);
                sv[4 * j + 0] = s.x + e.x;
                sv[4 * j + 1] = s.y + e.y;
                sv[4 * j + 2] = s.z + e.z;
                sv[4 * j + 3] = s.w + e.w;
            }
            float mx = -1e30f;
#pragma unroll
            for (int j = 0; j < 16; j++) mx = fmaxf(mx, sv[j]);
            mx = fmaxf(mx, __shfl_xor_sync(0xffffffffu, mx, 1));
            mx = fmaxf(mx, __shfl_xor_sync(0xffffffffu, mx, 2));
            const float mold = rM[r];
            const float mnew = fmaxf(mold, mx);
            float sum = 0.f;
#pragma unroll
            for (int j = 0; j < 16; j++) {
                float p = __expf(sv[j] - mnew);
                sum += p;
                sv[j] = p;
            }
            sum += __shfl_xor_sync(0xffffffffu, sum, 1);
            sum += __shfl_xor_sync(0xffffffffu, sum, 2);
#pragma unroll
            for (int j = 0; j < 4; j++) {
                *(uint4*)(srow + j * 4) =
                    make_uint4(f2tf(sv[4 * j + 0]), f2tf(sv[4 * j + 1]),
                               f2tf(sv[4 * j + 2]), f2tf(sv[4 * j + 3]));
            }
            if (sub == 0) {
                const float corr = __expf(mold - mnew);
                rC[r] = corr;
                rM[r] = mnew;
                rL[r] = rL[r] * corr + sum;
            }
        }
        __syncthreads();

        const float c0 = rC[wm + g], c1 = rC[wm + 8 + g];
#pragma unroll
        for (int nf = 0; nf < 16; nf++) {
            o[nf][0] *= c0; o[nf][1] *= c0;
            o[nf][2] *= c1; o[nf][3] *= c1;
        }
#pragma unroll
        for (int ks = 0; ks < 8; ks++) {
            const int k0 = ks * 8;
            unsigned af[4];
            const float* pa = Ss + (wm + g) * SSTR + k0 + t4;
            af[0] = __float_as_uint(pa[0]);
            af[1] = __float_as_uint(pa[8 * SSTR]);
            af[2] = __float_as_uint(pa[4]);
            af[3] = __float_as_uint(pa[8 * SSTR + 4]);
#pragma unroll
            for (int nf = 0; nf < 16; nf++) {
                unsigned bf[2];
                const float* pb = Vs + (k0 + t4) * VSTR + wn + nf * 8 + g;
                bf[0] = __float_as_uint(pb[0]);
                bf[1] = __float_as_uint(pb[4 * VSTR]);
                MMA8(o[nf], af, bf);
            }
        }
    }

    const float l0 = 1.f / rL[wm + g];
    const float l1 = 1.f / rL[wm + 8 + g];
#pragma unroll
    for (int nf = 0; nf < 16; nf++) {
        const int cc = wn + nf * 8 + 2 * t4;
        *(float2*)(og + (size_t)(wm + g) * 4096 + cc) =
            make_float2(o[nf][0] * l0, o[nf][1] * l0);
        *(float2*)(og + (size_t)(wm + 8 + g) * 4096 + cc) =
            make_float2(o[nf][2] * l1, o[nf][3] * l1);
    }
}

// ---------------- launch ------------------------------------------------------
extern "C" void kernel_launch(void* const* d_in, const int* in_sizes, int n_in,
                              void* d_out, int out_size) {
    (void)in_sizes; (void)n_in; (void)out_size;
    const float* x   = (const float*)d_in[0];
    const float* aug = (const float*)d_in[1];
    const float* Wq  = (const float*)d_in[2];
    const float* Wk  = (const float*)d_in[3];
    const float* Wv  = (const float*)d_in[4];
    const float* Wp  = (const float*)d_in[5];
    const float* bp  = (const float*)d_in[6];
    float* out = (float*)d_out;

    float *gq, *gk, *gv, *gep;
    cudaGetSymbolAddress((void**)&gq, g_q);
    cudaGetSymbolAddress((void**)&gk, g_k);
    cudaGetSymbolAddress((void**)&gv, g_v);
    cudaGetSymbolAddress((void**)&gep, g_ep);

    cudaFuncSetAttribute(gemm_tf32, cudaFuncAttributeMaxDynamicSharedMemorySize, GEMM_SMEM);
    cudaFuncSetAttribute(attn_tf32, cudaFuncAttributeMaxDynamicSharedMemorySize, ATTN_SMEM);

    dim3 blk(256);
    dim3 gqkv(4096 / GBN, 8192 / GBM);
    gemm_tf32<<<gqkv, blk, GEMM_SMEM>>>(x, Wq, nullptr, gq, 8192, 4096, 4096);
    gemm_tf32<<<gqkv, blk, GEMM_SMEM>>>(x, Wk, nullptr, gk, 8192, 4096, 4096);
    gemm_tf32<<<gqkv, blk, GEMM_SMEM>>>(x, Wv, nullptr, gv, 8192, 4096, 4096);

    dim3 gep_grid(8192 / GBN, 8192 / GBM);
    gemm_tf32<<<gep_grid, blk, GEMM_SMEM>>>(aug, Wp, bp, gep, 8192, 8192, 4096);

    dim3 gattn(512 / AQ, 16 * 16);
    attn_tf32<<<gattn, blk, ATTN_SMEM>>>(gq, gk, gv, gep, out);
}

// round 5
// speedup vs baseline: 1.1545x; 1.1545x over previous
#include <cuda_runtime.h>
#include <math.h>
#include <cstdint>

// ---------------- scratch (device globals; no allocations allowed) ----------
__device__ float g_q[8192 * 4096];
__device__ float g_k[8192 * 4096];
__device__ float g_v[8192 * 4096];
__device__ float g_ep[67108864]; // 8192*8192
// RNA-rounded (tf32-exact) copies of GEMM operands
__device__ float g_xr[8192 * 4096];
__device__ float g_ar[8192 * 4096];
__device__ float g_wq[4096 * 4096];
__device__ float g_wk[4096 * 4096];
__device__ float g_wv[4096 * 4096];
__device__ float g_wp[8192 * 4096];

// ---------------- helpers ----------------------------------------------------
__device__ __forceinline__ unsigned f2tf(float x) {
    unsigned u;
    asm("cvt.rna.tf32.f32 %0, %1;" : "=r"(u) : "f"(x));
    return u;
}
__device__ __forceinline__ void cpasync16(unsigned saddr, const float* gaddr) {
    asm volatile("cp.async.cg.shared.global [%0], [%1], 16;\n" ::"r"(saddr), "l"(gaddr));
}
__device__ __forceinline__ void cp_commit() {
    asm volatile("cp.async.commit_group;\n" ::);
}
template <int N>
__device__ __forceinline__ void cp_wait() {
    asm volatile("cp.async.wait_group %0;\n" ::"n"(N));
}

#define MMA8(C, A, Bv)                                                         \
    asm volatile(                                                              \
        "mma.sync.aligned.m16n8k8.row.col.f32.tf32.tf32.f32 "                  \
        "{%0,%1,%2,%3}, {%4,%5,%6,%7}, {%8,%9}, {%0,%1,%2,%3};"                \
        : "+f"(C[0]), "+f"(C[1]), "+f"(C[2]), "+f"(C[3])                       \
        : "r"(A[0]), "r"(A[1]), "r"(A[2]), "r"(A[3]), "r"(Bv[0]), "r"(Bv[1]))

// ---------------- pre-round inputs to tf32 (RNA) ------------------------------
__global__ void round_tf32(const float* __restrict__ in, float* __restrict__ out, int n4) {
    int i = blockIdx.x * blockDim.x + threadIdx.x;
    if (i < n4) {
        float4 v = ((const float4*)in)[i];
        ((uint4*)out)[i] = make_uint4(f2tf(v.x), f2tf(v.y), f2tf(v.z), f2tf(v.w));
    }
}

// ---------------- GEMM: C[M,N] = A[M,K] * B[N,K]^T (+bias[n]) ---------------
// Inputs pre-rounded to tf32-exact fp32 -> NO cvt in the hot loop.
// 128x128 block tile, cp.async 5-stage (K=16/stage), 8 warps, 64x32 warp tile,
// 2 CTAs/SM.
#define GBM 128
#define GBN 128
#define GKS 16
#define NSTAGE 5
#define RPAD 20
#define ASTG (GBM * RPAD)
#define GEMM_SMEM (2 * NSTAGE * ASTG * 4) // 102400 B

__global__ void __launch_bounds__(256, 2)
    gemm_tf32(const float* __restrict__ A, const float* __restrict__ B,
              const float* __restrict__ bias, float* __restrict__ C,
              int M, int N, int K) {
    extern __shared__ float sm[];
    float* As = sm;
    float* Bs = sm + NSTAGE * ASTG;

    const unsigned smA_u = (unsigned)__cvta_generic_to_shared(As);
    const unsigned smB_u = (unsigned)__cvta_generic_to_shared(Bs);

    const int tid = threadIdx.x;
    const int lane = tid & 31;
    const int wid = tid >> 5;
    const int g = lane >> 2;
    const int t4 = lane & 3;
    const int wm = (wid & 1) * 64;
    const int wn = (wid >> 1) * 32;

    const int bm = blockIdx.y * GBM;
    const int bn = blockIdx.x * GBN;

    const int r0 = tid >> 2;
    const int r1 = r0 + 64;
    const int c0 = (tid & 3) * 4;

    const float* Ag0 = A + (size_t)(bm + r0) * K + c0;
    const float* Ag1 = A + (size_t)(bm + r1) * K + c0;
    const float* Bg0 = B + (size_t)(bn + r0) * K + c0;
    const float* Bg1 = B + (size_t)(bn + r1) * K + c0;

    const unsigned sA0 = smA_u + (unsigned)(r0 * RPAD + c0) * 4u;
    const unsigned sA1 = smA_u + (unsigned)(r1 * RPAD + c0) * 4u;
    const unsigned sB0 = smB_u + (unsigned)(r0 * RPAD + c0) * 4u;
    const unsigned sB1 = smB_u + (unsigned)(r1 * RPAD + c0) * 4u;

    const int NT = K / GKS;
    const unsigned stg_b = ASTG * 4u;

#pragma unroll
    for (int s = 0; s < NSTAGE - 1; s++) {
        const size_t ko = (size_t)s * GKS;
        cpasync16(sA0 + s * stg_b, Ag0 + ko);
        cpasync16(sA1 + s * stg_b, Ag1 + ko);
        cpasync16(sB0 + s * stg_b, Bg0 + ko);
        cpasync16(sB1 + s * stg_b, Bg1 + ko);
        cp_commit();
    }

    float c[4][4][4];
#pragma unroll
    for (int i = 0; i < 4; i++)
#pragma unroll
        for (int j = 0; j < 4; j++)
#pragma unroll
            for (int q = 0; q < 4; q++) c[i][j][q] = 0.f;

    int stage = 0;
    for (int kt = 0; kt < NT; kt++) {
        cp_wait<NSTAGE - 2>();
        __syncthreads();

        {
            const int kf = kt + NSTAGE - 1;
            if (kf < NT) {
                const int sw = (stage + NSTAGE - 1 >= NSTAGE) ? stage - 1
                                                              : stage + NSTAGE - 1;
                const size_t ko = (size_t)kf * GKS;
                const unsigned so = sw * stg_b;
                cpasync16(sA0 + so, Ag0 + ko);
                cpasync16(sA1 + so, Ag1 + ko);
                cpasync16(sB0 + so, Bg0 + ko);
                cpasync16(sB1 + so, Bg1 + ko);
            }
            cp_commit();
        }

        const float* as = As + stage * ASTG;
        const float* bs = Bs + stage * ASTG;
#pragma unroll
        for (int ks = 0; ks < 2; ks++) {
            const int k0 = ks * 8;
            unsigned af[4][4], bf[4][2];
#pragma unroll
            for (int mf = 0; mf < 4; mf++) {
                const float* p = as + (wm + mf * 16 + g) * RPAD + k0 + t4;
                af[mf][0] = __float_as_uint(p[0]);
                af[mf][1] = __float_as_uint(p[8 * RPAD]);
                af[mf][2] = __float_as_uint(p[4]);
                af[mf][3] = __float_as_uint(p[8 * RPAD + 4]);
            }
#pragma unroll
            for (int nf = 0; nf < 4; nf++) {
                const float* p = bs + (wn + nf * 8 + g) * RPAD + k0 + t4;
                bf[nf][0] = __float_as_uint(p[0]);
                bf[nf][1] = __float_as_uint(p[4]);
            }
#pragma unroll
            for (int mf = 0; mf < 4; mf++)
#pragma unroll
                for (int nf = 0; nf < 4; nf++) MMA8(c[mf][nf], af[mf], bf[nf]);
        }
        stage = (stage + 1 == NSTAGE) ? 0 : stage + 1;
    }

#pragma unroll
    for (int mf = 0; mf < 4; mf++) {
        const int r = bm + wm + mf * 16 + g;
#pragma unroll
        for (int nf = 0; nf < 4; nf++) {
            const int col = bn + wn + nf * 8 + 2 * t4;
            float b0 = 0.f, b1 = 0.f;
            if (bias) { b0 = bias[col]; b1 = bias[col + 1]; }
            *(float2*)(C + (size_t)r * N + col) =
                make_float2(c[mf][nf][0] + b0, c[mf][nf][1] + b1);
            *(float2*)(C + (size_t)(r + 8) * N + col) =
                make_float2(c[mf][nf][2] + b0, c[mf][nf][3] + b1);
        }
    }
}

// ---------------- fused attention (unchanged, known-correct) -----------------
#define AQ 64
#define AS 64
#define QSTR 260
#define KSTR 260
#define VSTR 264
#define SSTR 68
#define ATTN_SMEM ((AQ * QSTR + AS * KSTR + AS * VSTR + AQ * SSTR + 3 * AQ) * 4)

__global__ void __launch_bounds__(256, 1)
    attn_tf32(const float* __restrict__ Q, const float* __restrict__ Kk,
              const float* __restrict__ V, const float* __restrict__ EP,
              float* __restrict__ O) {
    extern __shared__ float sm[];
    float* Qs = sm;
    float* Ks = Qs + AQ * QSTR;
    float* Vs = Ks + AS * KSTR;
    float* Ss = Vs + AS * VSTR;
    float* rM = Ss + AQ * SSTR;
    float* rL = rM + AQ;
    float* rC = rL + AQ;

    const int tid = threadIdx.x;
    const int lane = tid & 31;
    const int wid = tid >> 5;
    const int g = lane >> 2, t4 = lane & 3;
    const int wm = (wid & 3) * 16;
    const int wn = (wid >> 2) * 128;
    const int wns = (wid >> 2) * 32;

    const int b = blockIdx.y >> 4;
    const int h = blockIdx.y & 15;
    const int q0 = blockIdx.x * AQ;

    const float* qg = Q + ((size_t)(b * 512 + q0)) * 4096 + h * 256;
    const float* kg = Kk + ((size_t)(b * 512)) * 4096 + h * 256;
    const float* vg = V + ((size_t)(b * 512)) * 4096 + h * 256;
    const float* eg = EP + ((size_t)(b * 512 + q0)) * 8192 + h * 512;
    float* og = O + ((size_t)(b * 512 + q0)) * 4096 + h * 256;

    const float qscale = 0.0625f; // 1/sqrt(256)
    for (int i = tid; i < AQ * 64; i += 256) {
        int r = i >> 6, ccol = (i & 63) << 2;
        float4 qv = *(const float4*)(qg + (size_t)r * 4096 + ccol);
        *(uint4*)(Qs + r * QSTR + ccol) =
            make_uint4(f2tf(qv.x * qscale), f2tf(qv.y * qscale),
                       f2tf(qv.z * qscale), f2tf(qv.w * qscale));
    }
    if (tid < AQ) { rM[tid] = -1e30f; rL[tid] = 0.f; }

    float o[16][4];
#pragma unroll
    for (int nf = 0; nf < 16; nf++)
#pragma unroll
        for (int q = 0; q < 4; q++) o[nf][q] = 0.f;

    for (int kc = 0; kc < 8; kc++) {
        __syncthreads();
        for (int i = tid; i < AS * 64; i += 256) {
            int r = i >> 6, ccol = (i & 63) << 2;
            float4 kv = *(const float4*)(kg + (size_t)(kc * AS + r) * 4096 + ccol);
            float4 vv = *(const float4*)(vg + (size_t)(kc * AS + r) * 4096 + ccol);
            *(uint4*)(Ks + r * KSTR + ccol) =
                make_uint4(f2tf(kv.x), f2tf(kv.y), f2tf(kv.z), f2tf(kv.w));
            *(uint4*)(Vs + r * VSTR + ccol) =
                make_uint4(f2tf(vv.x), f2tf(vv.y), f2tf(vv.z), f2tf(vv.w));
        }
        __syncthreads();

        float sacc[4][4];
#pragma unroll
        for (int nf = 0; nf < 4; nf++)
#pragma unroll
            for (int q = 0; q < 4; q++) sacc[nf][q] = 0.f;
#pragma unroll
        for (int ks = 0; ks < 32; ks++) {
            const int k0 = ks * 8;
            unsigned af[4];
            const float* pa = Qs + (wm + g) * QSTR + k0 + t4;
            af[0] = __float_as_uint(pa[0]);
            af[1] = __float_as_uint(pa[8 * QSTR]);
            af[2] = __float_as_uint(pa[4]);
            af[3] = __float_as_uint(pa[8 * QSTR + 4]);
#pragma unroll
            for (int nf = 0; nf < 4; nf++) {
                unsigned bf[2];
                const float* pb = Ks + (wns + nf * 8 + g) * KSTR + k0 + t4;
                bf[0] = __float_as_uint(pb[0]);
                bf[1] = __float_as_uint(pb[4]);
                MMA8(sacc[nf], af, bf);
            }
        }
#pragma unroll
        for (int nf = 0; nf < 4; nf++) {
            const int cc = wns + nf * 8 + 2 * t4;
            *(float2*)(Ss + (wm + g) * SSTR + cc) = make_float2(sacc[nf][0], sacc[nf][1]);
            *(float2*)(Ss + (wm + 8 + g) * SSTR + cc) = make_float2(sacc[nf][2], sacc[nf][3]);
        }
        __syncthreads();

        {
            const int r = tid >> 2, sub = tid & 3;
            float sv[16];
            const float* ep4 = eg + (size_t)r * 8192 + kc * 64 + sub * 16;
            float* srow = Ss + r * SSTR + sub * 16;
#pragma unroll
            for (int j = 0; j < 4; j++) {
                float4 e = *(const float4*)(ep4 + j * 4);
                float4 s = *(const float4*)(srow + j * 4);
                sv[4 * j + 0] = s.x + e.x;
                sv[4 * j + 1] = s.y + e.y;
                sv[4 * j + 2] = s.z + e.z;
                sv[4 * j + 3] = s.w + e.w;
            }
            float mx = -1e30f;
#pragma unroll
            for (int j = 0; j < 16; j++) mx = fmaxf(mx, sv[j]);
            mx = fmaxf(mx, __shfl_xor_sync(0xffffffffu, mx, 1));
            mx = fmaxf(mx, __shfl_xor_sync(0xffffffffu, mx, 2));
            const float mold = rM[r];
            const float mnew = fmaxf(mold, mx);
            float sum = 0.f;
#pragma unroll
            for (int j = 0; j < 16; j++) {
                float p = __expf(sv[j] - mnew);
                sum += p;
                sv[j] = p;
            }
            sum += __shfl_xor_sync(0xffffffffu, sum, 1);
            sum += __shfl_xor_sync(0xffffffffu, sum, 2);
#pragma unroll
            for (int j = 0; j < 4; j++) {
                *(uint4*)(srow + j * 4) =
                    make_uint4(f2tf(sv[4 * j + 0]), f2tf(sv[4 * j + 1]),
                               f2tf(sv[4 * j + 2]), f2tf(sv[4 * j + 3]));
            }
            if (sub == 0) {
                const float corr = __expf(mold - mnew);
                rC[r] = corr;
                rM[r] = mnew;
                rL[r] = rL[r] * corr + sum;
            }
        }
        __syncthreads();

        const float c0 = rC[wm + g], c1 = rC[wm + 8 + g];
#pragma unroll
        for (int nf = 0; nf < 16; nf++) {
            o[nf][0] *= c0; o[nf][1] *= c0;
            o[nf][2] *= c1; o[nf][3] *= c1;
        }
#pragma unroll
        for (int ks = 0; ks < 8; ks++) {
            const int k0 = ks * 8;
            unsigned af[4];
            const float* pa = Ss + (wm + g) * SSTR + k0 + t4;
            af[0] = __float_as_uint(pa[0]);
            af[1] = __float_as_uint(pa[8 * SSTR]);
            af[2] = __float_as_uint(pa[4]);
            af[3] = __float_as_uint(pa[8 * SSTR + 4]);
#pragma unroll
            for (int nf = 0; nf < 16; nf++) {
                unsigned bf[2];
                const float* pb = Vs + (k0 + t4) * VSTR + wn + nf * 8 + g;
                bf[0] = __float_as_uint(pb[0]);
                bf[1] = __float_as_uint(pb[4 * VSTR]);
                MMA8(o[nf], af, bf);
            }
        }
    }

    const float l0 = 1.f / rL[wm + g];
    const float l1 = 1.f / rL[wm + 8 + g];
#pragma unroll
    for (int nf = 0; nf < 16; nf++) {
        const int cc = wn + nf * 8 + 2 * t4;
        *(float2*)(og + (size_t)(wm + g) * 4096 + cc) =
            make_float2(o[nf][0] * l0, o[nf][1] * l0);
        *(float2*)(og + (size_t)(wm + 8 + g) * 4096 + cc) =
            make_float2(o[nf][2] * l1, o[nf][3] * l1);
    }
}

// ---------------- launch ------------------------------------------------------
extern "C" void kernel_launch(void* const* d_in, const int* in_sizes, int n_in,
                              void* d_out, int out_size) {
    (void)in_sizes; (void)n_in; (void)out_size;
    const float* x   = (const float*)d_in[0];
    const float* aug = (const float*)d_in[1];
    const float* Wq  = (const float*)d_in[2];
    const float* Wk  = (const float*)d_in[3];
    const float* Wv  = (const float*)d_in[4];
    const float* Wp  = (const float*)d_in[5];
    const float* bp  = (const float*)d_in[6];
    float* out = (float*)d_out;

    float *gq, *gk, *gv, *gep, *gxr, *gar, *gwq, *gwk, *gwv, *gwp;
    cudaGetSymbolAddress((void**)&gq, g_q);
    cudaGetSymbolAddress((void**)&gk, g_k);
    cudaGetSymbolAddress((void**)&gv, g_v);
    cudaGetSymbolAddress((void**)&gep, g_ep);
    cudaGetSymbolAddress((void**)&gxr, g_xr);
    cudaGetSymbolAddress((void**)&gar, g_ar);
    cudaGetSymbolAddress((void**)&gwq, g_wq);
    cudaGetSymbolAddress((void**)&gwk, g_wk);
    cudaGetSymbolAddress((void**)&gwv, g_wv);
    cudaGetSymbolAddress((void**)&gwp, g_wp);

    cudaFuncSetAttribute(gemm_tf32, cudaFuncAttributeMaxDynamicSharedMemorySize, GEMM_SMEM);
    cudaFuncSetAttribute(attn_tf32, cudaFuncAttributeMaxDynamicSharedMemorySize, ATTN_SMEM);

    // 1) RNA-round GEMM operands to tf32-exact fp32 (removes cvt from hot loop)
    const int n_xd = 8192 * 4096 / 4, n_w = 4096 * 4096 / 4;
    round_tf32<<<(n_xd + 255) / 256, 256>>>(x, gxr, n_xd);
    round_tf32<<<(n_xd + 255) / 256, 256>>>(aug, gar, n_xd);
    round_tf32<<<(n_w + 255) / 256, 256>>>(Wq, gwq, n_w);
    round_tf32<<<(n_w + 255) / 256, 256>>>(Wk, gwk, n_w);
    round_tf32<<<(n_w + 255) / 256, 256>>>(Wv, gwv, n_w);
    round_tf32<<<(n_xd + 255) / 256, 256>>>(Wp, gwp, n_xd);

    // 2) GEMMs (mma.sync tf32, cvt-free hot loop)
    dim3 blk(256);
    dim3 gqkv(4096 / GBN, 8192 / GBM);
    gemm_tf32<<<gqkv, blk, GEMM_SMEM>>>(gxr, gwq, nullptr, gq, 8192, 4096, 4096);
    gemm_tf32<<<gqkv, blk, GEMM_SMEM>>>(gxr, gwk, nullptr, gk, 8192, 4096, 4096);
    gemm_tf32<<<gqkv, blk, GEMM_SMEM>>>(gxr, gwv, nullptr, gv, 8192, 4096, 4096);
    dim3 gep_grid(8192 / GBN, 8192 / GBM);
    gemm_tf32<<<gep_grid, blk, GEMM_SMEM>>>(gar, gwp, bp, gep, 8192, 8192, 4096);

    // 3) fused attention
    dim3 gattn(512 / AQ, 16 * 16);
    attn_tf32<<<gattn, blk, ATTN_SMEM>>>(gq, gk, gv, gep, out);
}